// round 12
// baseline (speedup 1.0000x reference)
#include <cuda_runtime.h>
#include <cuda_bf16.h>
#include <math_constants.h>
#include <mma.h>

using namespace nvcuda;

// Problem constants
#define B_    128
#define T_    1024
#define D_    512
#define V_    128
#define L_    128
#define S_    257           // 2L+1
#define BLANK_ 127          // V-1
#define EPS_  1e-7f
#define NEG_  (-1e30f)
#define LN2_  0.6931471805599453f

// GEMM tiling: 64x128 block tile, BK=16, 8 warps (4M x 2N), warp tile 16x64.
#define BM 64
#define BN 128
#define BK 16
#define NCHUNK (D_ / BK)    // 32
#define APAD 8
#define BPAD 8
#define CPAD 4

// Scratch: log2(softmax prob + eps) [B,T,V] fp32 (64 MB), per-example losses
static __device__ float g_lp[B_ * T_ * V_];
static __device__ float g_loss[B_];

__device__ __forceinline__ float fexp2(float x) {
    float y; asm("ex2.approx.ftz.f32 %0, %1;" : "=f"(y) : "f"(x)); return y;
}

__device__ __forceinline__ void st4bf16(__nv_bfloat16* dst, float4 v) {
    __nv_bfloat162 p0; p0.x = __float2bfloat16(v.x); p0.y = __float2bfloat16(v.y);
    __nv_bfloat162 p1; p1.x = __float2bfloat16(v.z); p1.y = __float2bfloat16(v.w);
    *(__nv_bfloat162*)(dst)     = p0;
    *(__nv_bfloat162*)(dst + 2) = p1;
}

// ---------------------------------------------------------------------------
// Kernel 1: bf16 WMMA GEMM (logits = X @ W + b) + softmax -> g_lp = log2(p+eps)
// M = 131072, N = 128, K = 512, fp32 accumulate.
// Small tile (BM=64) + __launch_bounds__(256,3): 3 CTAs/SM = 24 warps/SM so
// cross-CTA overlap fills the convoy stalls that capped the 128x128 variants.
// Per chunk: STS, bar, [LDG c+1 | MMA c], bar. Only 3 LDG.128/thread.
// ---------------------------------------------------------------------------
__global__ __launch_bounds__(256, 3) void gemm_softmax_kernel(
    const float* __restrict__ X, const float* __restrict__ W,
    const float* __restrict__ bias)
{
    __shared__ __align__(16) union {
        struct {
            __nv_bfloat16 A[BM][BK + APAD];    // 64 x 24 bf16 = 3072 B
            __nv_bfloat16 Bm[BK][BN + BPAD];   // 16 x 136 bf16 = 4352 B
        } st;
        float Cs[BM][BN + CPAD];               // 64 x 132 f32 = 33792 B
    } smem;

    const int tid = threadIdx.x;
    const int wid = tid >> 5;
    const int warp_m = wid & 3;       // 0..3 (16 rows each)
    const int warp_n = wid >> 2;      // 0..1 (64 cols each)
    const int rowBase = blockIdx.x * BM;

    wmma::fragment<wmma::accumulator, 16, 16, 16, float> cfrag[4];
#pragma unroll
    for (int j = 0; j < 4; ++j) wmma::fill_fragment(cfrag[j], 0.f);

    // Load mapping: A chunk 64x16 fp32 (4 thr/row, 1 float4 each);
    //               B chunk 16x128 fp32 (16 thr/row, 2 float4 each)
    const int ar = tid >> 2;
    const int ac = (tid & 3) * 4;
    const int br = tid >> 4;
    const int bc = (tid & 15) * 8;
    const float* Ap = X + (size_t)(rowBase + ar) * D_ + ac;
    const float* Bp = W + (size_t)br * V_ + bc;

    float4 ra, rb0, rb1;
#define LOAD_REGS(K0)                                                        \
    {   ra  = *(const float4*)(Ap + (K0));                                   \
        rb0 = *(const float4*)(Bp + (size_t)(K0) * V_);                      \
        rb1 = *(const float4*)(Bp + (size_t)(K0) * V_ + 4); }

    LOAD_REGS(0);

    for (int c = 0; c < NCHUNK; ++c) {
        st4bf16(&smem.st.A[ar][ac],   ra);
        st4bf16(&smem.st.Bm[br][bc],     rb0);
        st4bf16(&smem.st.Bm[br][bc + 4], rb1);
        __syncthreads();

        if (c + 1 < NCHUNK) LOAD_REGS((c + 1) * BK);   // overlaps MMA below

        wmma::fragment<wmma::matrix_a, 16, 16, 16, __nv_bfloat16, wmma::row_major> af;
        wmma::fragment<wmma::matrix_b, 16, 16, 16, __nv_bfloat16, wmma::row_major> bf[4];
        wmma::load_matrix_sync(af, &smem.st.A[warp_m * 16][0], BK + APAD);
#pragma unroll
        for (int j = 0; j < 4; ++j)
            wmma::load_matrix_sync(bf[j], &smem.st.Bm[0][warp_n * 64 + j * 16], BN + BPAD);
#pragma unroll
        for (int j = 0; j < 4; ++j)
            wmma::mma_sync(cfrag[j], af, bf[j], cfrag[j]);

        __syncthreads();   // MMA reads done before next iter's STS
    }
#undef LOAD_REGS

    // Epilogue: single pass, all 64 rows in Cs (aliases stage smem; safe after
    // the final barrier above). Softmax per row, write log2(p + eps).
#pragma unroll
    for (int j = 0; j < 4; ++j)
        wmma::store_matrix_sync(&smem.Cs[warp_m * 16][warp_n * 64 + j * 16],
                                cfrag[j], BN + CPAD, wmma::mem_row_major);
    __syncthreads();

    const int tx = tid & 15;          // 8 cols each
    const int ty = tid >> 4;          // 16 groups, 4 rows each
    float bb[8];
#pragma unroll
    for (int j = 0; j < 8; ++j) bb[j] = bias[tx * 8 + j];

#pragma unroll
    for (int r = 0; r < 4; ++r) {
        const int row = ty * 4 + r;
        float l[8];
        float rmax = -CUDART_INF_F;
#pragma unroll
        for (int j = 0; j < 8; ++j) {
            l[j] = smem.Cs[row][tx * 8 + j] + bb[j];
            rmax = fmaxf(rmax, l[j]);
        }
#pragma unroll
        for (int m = 1; m <= 8; m <<= 1)
            rmax = fmaxf(rmax, __shfl_xor_sync(0xFFFFFFFFu, rmax, m));
        float s = 0.f;
#pragma unroll
        for (int j = 0; j < 8; ++j) { l[j] = __expf(l[j] - rmax); s += l[j]; }
#pragma unroll
        for (int m = 1; m <= 8; m <<= 1)
            s += __shfl_xor_sync(0xFFFFFFFFu, s, m);
        float invs = 1.f / s;
        float* orow = g_lp + (size_t)(rowBase + row) * V_ + tx * 8;
        float4 o0, o1;
        o0.x = __log2f(l[0] * invs + EPS_); o0.y = __log2f(l[1] * invs + EPS_);
        o0.z = __log2f(l[2] * invs + EPS_); o0.w = __log2f(l[3] * invs + EPS_);
        o1.x = __log2f(l[4] * invs + EPS_); o1.y = __log2f(l[5] * invs + EPS_);
        o1.z = __log2f(l[6] * invs + EPS_); o1.w = __log2f(l[7] * invs + EPS_);
        *(float4*)orow = o0;
        *(float4*)(orow + 4) = o1;
    }
}

// ---------------------------------------------------------------------------
// Kernel 2: CTC forward DP, log2 domain (R7 version — fastest measured).
// One block per example, 288 threads, thread s owns state s (<257). Each
// state thread loads its own emission lp[t][myext] directly from global into
// a statically-indexed 8-deep FIFO (t-loop unrolled by 8 -> true depth 8).
// ---------------------------------------------------------------------------
__global__ __launch_bounds__(288) void ctc_kernel(
    const int* __restrict__ targets, const int* __restrict__ tlen)
{
    __shared__ float alpha[2][S_];
    __shared__ int   exts[S_];

    const int b = blockIdx.x;
    const int tid = threadIdx.x;
    const bool act = (tid < S_);
    const float* LP = g_lp + (size_t)b * T_ * V_;

    if (act) exts[tid] = (tid & 1) ? targets[b * L_ + (tid >> 1)] : BLANK_;
    __syncthreads();

    int  myext  = BLANK_;
    bool allow2 = false;
    if (act) {
        myext  = exts[tid];
        allow2 = (tid & 1) && (tid >= 2) && (myext != exts[tid - 2]);
    }

    // t = 0 init + prefetch FIFO for t = 1..8
    if (act) alpha[0][tid] = (tid < 2) ? LP[myext] : NEG_;
    float e[8];
#pragma unroll
    for (int j = 0; j < 8; ++j) e[j] = LP[(size_t)(1 + j) * V_ + myext];
    __syncthreads();

    // Main chunks: t0 = 1, 9, ..., 1009 (127 chunks, steps t = 1..1016).
    for (int t0 = 1; t0 <= T_ - 15; t0 += 8) {
#pragma unroll
        for (int j = 0; j < 8; ++j) {
            const int cur  = (1 + j) & 1;     // t0 odd -> parity is (1+j)&1
            const int prev = cur ^ 1;
            if (act) {
                float a  = alpha[prev][tid];
                float a1 = (tid >= 1) ? alpha[prev][tid - 1] : NEG_;
                float a2 = allow2 ? alpha[prev][tid - 2] : NEG_;
                float m  = fmaxf(fmaxf(a, a1), a2);
                float s  = fexp2(a - m) + fexp2(a1 - m) + fexp2(a2 - m);
                alpha[cur][tid] = m + __log2f(s) + e[j];
            }
            const int tn = t0 + 8 + j;        // prefetch for step t0+8+j
            if (tn < T_) e[j] = LP[(size_t)tn * V_ + myext];
            __syncthreads();
        }
    }
    // Tail: t = 1017..1023 (7 steps), emissions already in e[0..6].
#pragma unroll
    for (int j = 0; j < 7; ++j) {
        const int cur  = (1017 + j) & 1;
        const int prev = cur ^ 1;
        if (act) {
            float a  = alpha[prev][tid];
            float a1 = (tid >= 1) ? alpha[prev][tid - 1] : NEG_;
            float a2 = allow2 ? alpha[prev][tid - 2] : NEG_;
            float m  = fmaxf(fmaxf(a, a1), a2);
            float s  = fexp2(a - m) + fexp2(a1 - m) + fexp2(a2 - m);
            alpha[cur][tid] = m + __log2f(s) + e[j];
        }
        __syncthreads();
    }

    if (tid == 0) {
        const int last = 2 * tlen[b];              // 32..256
        // t = 1023 is odd -> final alpha lives in buffer 1.
        float aN  = alpha[1][last];
        float aN1 = alpha[1][last - 1];
        float m   = fmaxf(aN, aN1);
        g_loss[b] = -LN2_ * (m + __log2f(fexp2(aN - m) + fexp2(aN1 - m)));
    }
}

// ---------------------------------------------------------------------------
// Kernel 3: deterministic fixed-order sum of the 128 losses.
// ---------------------------------------------------------------------------
__global__ __launch_bounds__(128) void sum_kernel(float* __restrict__ out)
{
    __shared__ float s[128];
    const int t = threadIdx.x;
    s[t] = g_loss[t];
    __syncthreads();
    for (int o = 64; o > 0; o >>= 1) {
        if (t < o) s[t] += s[t + o];
        __syncthreads();
    }
    if (t == 0) out[0] = s[0];
}

extern "C" void kernel_launch(void* const* d_in, const int* in_sizes, int n_in,
                              void* d_out, int out_size)
{
    (void)in_sizes; (void)n_in; (void)out_size;
    const float* x       = (const float*)d_in[0];
    const float* W       = (const float*)d_in[1];
    const float* bias    = (const float*)d_in[2];
    const int*   targets = (const int*)d_in[3];
    const int*   tlength = (const int*)d_in[4];

    gemm_softmax_kernel<<<(B_ * T_) / BM, 256>>>(x, W, bias);
    ctc_kernel<<<B_, 288>>>(targets, tlength);
    sum_kernel<<<1, 128>>>((float*)d_out);
}